// round 16
// baseline (speedup 1.0000x reference)
#include <cuda_runtime.h>
#include <cuda_bf16.h>
#include <cstdint>
#include <cstddef>

#define N_NODES 50000
#define NUM_REL 8
#define IN_DIM  128
#define HID     256
#define E_EDGES 1600000
#define M_DEC   200000
#define NKEYS   (N_NODES * NUM_REL)      // 400000

// ---------------------------------------------------------------------------
// Device scratch. Packed format ("ps32"): one uint32 per element =
// (bf16(lo) << 16) | bf16(hi), hi = bf16(x), lo = bf16(x - float(hi)).
// ---------------------------------------------------------------------------
__device__ int      g_deg[NKEYS];
__device__ int      g_off[NKEYS];
__device__ int      g_cur[NKEYS];
__device__ int      g_srcs[E_EDGES];
__device__ int      g_bsums[512];
__device__ uint32_t g_A[(size_t)N_NODES * (HID + NUM_REL * HID)];   // packed, N x 2304 (layer1: N x 1152)
__device__ uint32_t g_B1[1152 * HID];            // layer1 weights [k][n] packed
__device__ uint32_t g_B2[2304 * HID];            // layer2 weights [k][n] packed
__device__ uint32_t g_Bd[HID * 2 * HID];         // decoder W1' (256 x 512) packed
__device__ uint32_t g_Bw2[HID * (HID / 2)];      // decoder W2  (256 x 128) packed
__device__ float    g_hp[(size_t)N_NODES * HID];
__device__ float    g_h1[(size_t)N_NODES * HID];                    // fp32 h1 (dense, L2-hot)
__device__ uint32_t g_hP[(size_t)N_NODES * HID];                    // packed final h
__device__ float    g_P [(size_t)N_NODES * 2 * HID];                // 50000 x 512
__device__ uint32_t g_Z1[(size_t)M_DEC * HID];                      // packed

// ---------------------------------------------------------------------------
__device__ __forceinline__ uint32_t bf16_split_pack(float x) {
    __nv_bfloat16 h = __float2bfloat16(x);
    float hf = __bfloat162float(h);
    __nv_bfloat16 l = __float2bfloat16(x - hf);
    return ((uint32_t)__bfloat16_as_ushort(l) << 16) | (uint32_t)__bfloat16_as_ushort(h);
}

__global__ void zero_int_kernel(int* __restrict__ p, int n4) {
    int i = blockIdx.x * blockDim.x + threadIdx.x;
    if (i < n4) ((int4*)p)[i] = make_int4(0, 0, 0, 0);
}

// ---------------------------------------------------------------------------
// CSR build over keys (dst*8 + rel)
// ---------------------------------------------------------------------------
__global__ void hist_kernel(const int* __restrict__ ei, const int* __restrict__ et) {
    int e = blockIdx.x * blockDim.x + threadIdx.x;
    if (e >= E_EDGES) return;
    int key = ei[E_EDGES + e] * NUM_REL + et[e];
    atomicAdd(&g_deg[key], 1);
}

__global__ void scan1_kernel(const int* __restrict__ in, int* __restrict__ out, int n) {
    __shared__ int s[256];
    int t = threadIdx.x;
    int base = blockIdx.x * 1024 + t * 4;
    int v0 = 0, v1 = 0, v2 = 0, v3 = 0;
    if (base + 0 < n) v0 = in[base + 0];
    if (base + 1 < n) v1 = in[base + 1];
    if (base + 2 < n) v2 = in[base + 2];
    if (base + 3 < n) v3 = in[base + 3];
    int tsum = v0 + v1 + v2 + v3;
    s[t] = tsum;
    __syncthreads();
    for (int o = 1; o < 256; o <<= 1) {
        int x = (t >= o) ? s[t - o] : 0;
        __syncthreads();
        s[t] += x;
        __syncthreads();
    }
    int excl = s[t] - tsum;
    if (t == 255) g_bsums[blockIdx.x] = s[255];
    if (base + 0 < n) out[base + 0] = excl;
    if (base + 1 < n) out[base + 1] = excl + v0;
    if (base + 2 < n) out[base + 2] = excl + v0 + v1;
    if (base + 3 < n) out[base + 3] = excl + v0 + v1 + v2;
}

__global__ void scan2_kernel(int nb) {
    __shared__ int s[512];
    int t = threadIdx.x;
    int v = (t < nb) ? g_bsums[t] : 0;
    s[t] = v;
    __syncthreads();
    for (int o = 1; o < 512; o <<= 1) {
        int x = (t >= o) ? s[t - o] : 0;
        __syncthreads();
        s[t] += x;
        __syncthreads();
    }
    if (t < nb) g_bsums[t] = s[t] - v;   // exclusive
}

__global__ void scan3_kernel(int* __restrict__ off, int* __restrict__ cur, int n) {
    int i = blockIdx.x * blockDim.x + threadIdx.x;
    if (i >= n) return;
    int o = off[i] + g_bsums[i >> 10];
    off[i] = o;
    cur[i] = o;
}

__global__ void fill_kernel(const int* __restrict__ ei, const int* __restrict__ et) {
    int e = blockIdx.x * blockDim.x + threadIdx.x;
    if (e >= E_EDGES) return;
    int key = ei[E_EDGES + e] * NUM_REL + et[e];
    int p = atomicAdd(&g_cur[key], 1);
    g_srcs[p] = ei[e];
}

// ---------------------------------------------------------------------------
// Gather-reduce aggregation (one warp per (node, rel) key) → packed mean into
// g_A[n, (1+r)*DIN : (2+r)*DIN].  fp32 inputs (precision floor: ps32 or fp32).
// ---------------------------------------------------------------------------
template <int DIN>
__global__ void gather_agg_kernel(const float* __restrict__ feat) {
    const int K = DIN * (NUM_REL + 1);
    int w = (blockIdx.x * blockDim.x + threadIdx.x) >> 5;
    int lane = threadIdx.x & 31;
    if (w >= NKEYS) return;
    int n = w >> 3;
    int r = w & 7;
    int off = g_off[w];
    int cnt = g_deg[w];

    float4 a0 = make_float4(0.f, 0.f, 0.f, 0.f);
    float4 a1 = make_float4(0.f, 0.f, 0.f, 0.f);

    int i = 0;
    for (; i + 2 <= cnt; i += 2) {
        int s0 = g_srcs[off + i];
        int s1 = g_srcs[off + i + 1];
        const float4* p0 = (const float4*)(feat + (size_t)s0 * DIN) + lane;
        const float4* p1 = (const float4*)(feat + (size_t)s1 * DIN) + lane;
        float4 v0 = __ldg(p0);
        float4 v1 = __ldg(p1);
        float4 u0, u1;
        if (DIN == 256) { u0 = __ldg(p0 + 32); u1 = __ldg(p1 + 32); }
        a0.x += v0.x + v1.x; a0.y += v0.y + v1.y;
        a0.z += v0.z + v1.z; a0.w += v0.w + v1.w;
        if (DIN == 256) {
            a1.x += u0.x + u1.x; a1.y += u0.y + u1.y;
            a1.z += u0.z + u1.z; a1.w += u0.w + u1.w;
        }
    }
    if (i < cnt) {
        int s0 = g_srcs[off + i];
        const float4* p0 = (const float4*)(feat + (size_t)s0 * DIN) + lane;
        float4 v0 = __ldg(p0);
        a0.x += v0.x; a0.y += v0.y; a0.z += v0.z; a0.w += v0.w;
        if (DIN == 256) {
            float4 u0 = __ldg(p0 + 32);
            a1.x += u0.x; a1.y += u0.y; a1.z += u0.z; a1.w += u0.w;
        }
    }

    float sc = 1.0f / fmaxf((float)cnt, 1.0f);
    uint4 o0;
    o0.x = bf16_split_pack(a0.x * sc);
    o0.y = bf16_split_pack(a0.y * sc);
    o0.z = bf16_split_pack(a0.z * sc);
    o0.w = bf16_split_pack(a0.w * sc);
    uint4* dst = (uint4*)(g_A + (size_t)n * K + (1 + r) * DIN) + lane;
    *dst = o0;
    if (DIN == 256) {
        uint4 o1;
        o1.x = bf16_split_pack(a1.x * sc);
        o1.y = bf16_split_pack(a1.y * sc);
        o1.z = bf16_split_pack(a1.z * sc);
        o1.w = bf16_split_pack(a1.w * sc);
        *(dst + 32) = o1;
    }
}

// Layer-1 root copy: x packed into A[:, 0:128] (stride 1152)
__global__ void copy_feat1_kernel(const float* __restrict__ feat) {
    const int K = 1152;
    const int L = IN_DIM / 4;
    int idx = blockIdx.x * blockDim.x + threadIdx.x;
    if (idx >= N_NODES * L) return;
    int n = idx / L;
    int j = idx % L;
    float4 v = *((const float4*)(feat + (size_t)n * IN_DIM) + j);
    uint4 o;
    o.x = bf16_split_pack(v.x);
    o.y = bf16_split_pack(v.y);
    o.z = bf16_split_pack(v.z);
    o.w = bf16_split_pack(v.w);
    *((uint4*)(g_A + (size_t)n * K) + j) = o;
}

// ---------------------------------------------------------------------------
// Weight builders ([k][n] packed), each to its own buffer
// ---------------------------------------------------------------------------
__global__ void build_B_kernel(const float* __restrict__ root,
                               const float* __restrict__ W, int Kin,
                               uint32_t* __restrict__ out) {
    int total = Kin * (NUM_REL + 1) * HID;
    int idx = blockIdx.x * blockDim.x + threadIdx.x;
    if (idx >= total) return;
    int rootN = Kin * HID;
    float v = (idx < rootN) ? root[idx] : W[idx - rootN];
    out[idx] = bf16_split_pack(v);
}

// Decoder B' (256 x 512): cols 0..255 = mw1_top, 256..511 = mw1_bot
__global__ void build_Bdec_kernel(const float* __restrict__ mw1) {
    int idx = blockIdx.x * blockDim.x + threadIdx.x;   // 256*512
    if (idx >= HID * 2 * HID) return;
    int k = idx >> 9;
    int n = idx & 511;
    float v = (n < HID) ? mw1[k * HID + n] : mw1[(HID + k) * HID + (n - HID)];
    g_Bd[idx] = bf16_split_pack(v);
}

__global__ void pack_w2_kernel(const float* __restrict__ mw2) {
    int idx = blockIdx.x * blockDim.x + threadIdx.x;
    if (idx >= HID * (HID / 2)) return;
    g_Bw2[idx] = bf16_split_pack(mw2[idx]);
}

// ---------------------------------------------------------------------------
// Packed-split BF16 GEMM, 3-term compensation, cp.async 3-STAGE pipeline.
// One __syncthreads per k-tile: the top barrier proves compute(t-1) is done,
// so issuing cp.async for tile t+2 (into buffer (t+2)%3 == (t-1)%3's successor)
// after it is safe. Buffers: compute t%3, in-flight (t+1)%3, issuing (t+2)%3.
// Dynamic smem: 3 * (128*20 + 16*132) * 4 = 56064 B; occ 2 preserved.
// ---------------------------------------------------------------------------
#define ASTRIDE 20
#define BSTRIDE 132
#define A_TILE_U32 (128 * ASTRIDE)            // 2560
#define B_TILE_U32 (16 * BSTRIDE)             // 2112
#define STAGE_U32  (A_TILE_U32 + B_TILE_U32)  // 4672
#define GEMM_SMEM_BYTES (3 * STAGE_U32 * 4)   // 56064

__device__ __forceinline__ void cp16(uint32_t smem, const void* g) {
    asm volatile("cp.async.cg.shared.global [%0], [%1], 16;" :: "r"(smem), "l"(g));
}

#define MMA_BF16(d, a, b)                                                     \
    asm volatile("mma.sync.aligned.m16n8k16.row.col.f32.bf16.bf16.f32 "       \
                 "{%0,%1,%2,%3}, {%4,%5,%6,%7}, {%8,%9}, {%0,%1,%2,%3};"      \
                 : "+f"(d[0]), "+f"(d[1]), "+f"(d[2]), "+f"(d[3])             \
                 : "r"(a[0]), "r"(a[1]), "r"(a[2]), "r"(a[3]),                \
                   "r"(b[0]), "r"(b[1]))

// Shared mainloop body for both GEMM kernels (macro to keep code identical).
// Produces acc[4][4][4]; expects ag/bg global pointers and smem stage bases.
#define GEMM_MAINLOOP(Kval, Nval)                                             \
    const int ntiles = (Kval) >> 4;                                           \
    cp16(aS[0],      ag);                                                     \
    cp16(aS[0] + 16, ag + 4);                                                 \
    cp16(bS[0],      bg);                                                     \
    cp16(bS[0] + 16, bg + 4);                                                 \
    asm volatile("cp.async.commit_group;");                                   \
    {                                                                         \
        int k1 = 16;                                                          \
        cp16(aS[1],      ag + k1);                                            \
        cp16(aS[1] + 16, ag + k1 + 4);                                        \
        cp16(bS[1],      bg + (size_t)k1 * (Nval));                           \
        cp16(bS[1] + 16, bg + (size_t)k1 * (Nval) + 4);                       \
        asm volatile("cp.async.commit_group;");                               \
    }                                                                         \
    for (int t = 0; t < ntiles; t++) {                                        \
        asm volatile("cp.async.wait_group 1;");                               \
        __syncthreads();                                                      \
        if (t + 2 < ntiles) {                                                 \
            int k0 = (t + 2) << 4;                                            \
            int s = (t + 2) % 3;                                              \
            cp16(aS[s],      ag + k0);                                        \
            cp16(aS[s] + 16, ag + k0 + 4);                                    \
            cp16(bS[s],      bg + (size_t)k0 * (Nval));                       \
            cp16(bS[s] + 16, bg + (size_t)k0 * (Nval) + 4);                   \
            asm volatile("cp.async.commit_group;");                           \
        } else {                                                              \
            asm volatile("cp.async.commit_group;");                           \
        }                                                                     \
        const uint32_t* as = smem + (t % 3) * STAGE_U32;                      \
        const uint32_t* bs = as + A_TILE_U32;                                 \
        uint32_t bh[4][2], bl[4][2];                                          \
        _Pragma("unroll")                                                     \
        for (int nt = 0; nt < 4; nt++) {                                      \
            int n = wn + nt * 8 + gid;                                        \
            uint32_t r0 = bs[(tig * 2 + 0) * BSTRIDE + n];                    \
            uint32_t r1 = bs[(tig * 2 + 1) * BSTRIDE + n];                    \
            uint32_t r2 = bs[(tig * 2 + 8) * BSTRIDE + n];                    \
            uint32_t r3 = bs[(tig * 2 + 9) * BSTRIDE + n];                    \
            bh[nt][0] = __byte_perm(r0, r1, 0x5410);                          \
            bh[nt][1] = __byte_perm(r2, r3, 0x5410);                          \
            bl[nt][0] = __byte_perm(r0, r1, 0x7632);                          \
            bl[nt][1] = __byte_perm(r2, r3, 0x7632);                          \
        }                                                                     \
        _Pragma("unroll")                                                     \
        for (int mt = 0; mt < 4; mt++) {                                      \
            int m0 = wm + mt * 16 + gid;                                      \
            uint2 p0 = *(const uint2*)&as[m0 * ASTRIDE + tig * 2];            \
            uint2 p1 = *(const uint2*)&as[(m0 + 8) * ASTRIDE + tig * 2];      \
            uint2 p2 = *(const uint2*)&as[m0 * ASTRIDE + tig * 2 + 8];        \
            uint2 p3 = *(const uint2*)&as[(m0 + 8) * ASTRIDE + tig * 2 + 8];  \
            uint32_t ah[4] = {__byte_perm(p0.x, p0.y, 0x5410),                \
                              __byte_perm(p1.x, p1.y, 0x5410),                \
                              __byte_perm(p2.x, p2.y, 0x5410),                \
                              __byte_perm(p3.x, p3.y, 0x5410)};               \
            uint32_t al[4] = {__byte_perm(p0.x, p0.y, 0x7632),                \
                              __byte_perm(p1.x, p1.y, 0x7632),                \
                              __byte_perm(p2.x, p2.y, 0x7632),                \
                              __byte_perm(p3.x, p3.y, 0x7632)};               \
            _Pragma("unroll")                                                 \
            for (int nt = 0; nt < 4; nt++) {                                  \
                MMA_BF16(acc[mt][nt], ah, bh[nt]);                            \
                MMA_BF16(acc[mt][nt], ah, bl[nt]);                            \
                MMA_BF16(acc[mt][nt], al, bh[nt]);                            \
            }                                                                 \
        }                                                                     \
    }                                                                         \
    asm volatile("cp.async.wait_group 0;");

__global__ __launch_bounds__(256, 2)
void gemm_ps_kernel(const uint32_t* __restrict__ A, const uint32_t* __restrict__ B,
                    float* __restrict__ C, const float* __restrict__ bias,
                    int M, int N, int K, int act) {
    extern __shared__ uint32_t smem[];

    const int tid  = threadIdx.x;
    const int warp = tid >> 5, lane = tid & 31;
    const int gid  = lane >> 2, tig = lane & 3;
    const int wm   = (warp & 1) * 64, wn = (warp >> 1) * 32;
    const int brow = blockIdx.y * 128, bcol = blockIdx.x * 128;

    float acc[4][4][4];
#pragma unroll
    for (int i = 0; i < 4; i++)
#pragma unroll
        for (int j = 0; j < 4; j++)
#pragma unroll
            for (int c = 0; c < 4; c++) acc[i][j][c] = 0.f;

    const int ar = tid >> 1;
    const int ac = (tid & 1) * 8;
    const int br = tid >> 4;
    const int bc = (tid & 15) * 8;

    const int arow_g = min(brow + ar, M - 1);
    const uint32_t* ag = A + (size_t)arow_g * K + ac;
    const uint32_t* bg = B + (size_t)br * N + bcol + bc;

    uint32_t aS[3], bS[3];
#pragma unroll
    for (int s = 0; s < 3; s++) {
        aS[s] = (uint32_t)__cvta_generic_to_shared(smem + s * STAGE_U32 + ar * ASTRIDE + ac);
        bS[s] = (uint32_t)__cvta_generic_to_shared(smem + s * STAGE_U32 + A_TILE_U32 + br * BSTRIDE + bc);
    }

    GEMM_MAINLOOP(K, N)

#pragma unroll
    for (int mt = 0; mt < 4; mt++) {
        int r0 = brow + wm + mt * 16 + gid;
#pragma unroll
        for (int nt = 0; nt < 4; nt++) {
            int c = bcol + wn + nt * 8 + 2 * tig;
            float bb0 = bias ? bias[c] : 0.f;
            float bb1 = bias ? bias[c + 1] : 0.f;
            float v0 = acc[mt][nt][0] + bb0;
            float v1 = acc[mt][nt][1] + bb1;
            float v2 = acc[mt][nt][2] + bb0;
            float v3 = acc[mt][nt][3] + bb1;
            if (act == 1) {
                const float is2 = 0.70710678118654752f;
                v0 = 0.5f * v0 * (1.0f + erff(v0 * is2));
                v1 = 0.5f * v1 * (1.0f + erff(v1 * is2));
                v2 = 0.5f * v2 * (1.0f + erff(v2 * is2));
                v3 = 0.5f * v3 * (1.0f + erff(v3 * is2));
            }
            if (r0 < M)
                *(float2*)(C + (size_t)r0 * N + c) = make_float2(v0, v1);
            if (r0 + 8 < M)
                *(float2*)(C + (size_t)(r0 + 8) * N + c) = make_float2(v2, v3);
        }
    }
}

// ---------------------------------------------------------------------------
// Z2 GEMM with FUSED final projection (3-stage pipeline):
//   out[m, 0:2] = gelu(Z1[m,:] @ W2 + b2) @ w3 + b3
// ---------------------------------------------------------------------------
__global__ __launch_bounds__(256, 2)
void gemm_z2_final_kernel(const uint32_t* __restrict__ A, const uint32_t* __restrict__ B,
                          const float* __restrict__ bias,
                          const float* __restrict__ w3, const float* __restrict__ b3,
                          float* __restrict__ out, int M, int K) {
    const int N = 128;
    extern __shared__ uint32_t smem[];

    const int tid  = threadIdx.x;
    const int warp = tid >> 5, lane = tid & 31;
    const int gid  = lane >> 2, tig = lane & 3;
    const int wm   = (warp & 1) * 64, wn = (warp >> 1) * 32;
    const int brow = blockIdx.y * 128;

    float acc[4][4][4];
#pragma unroll
    for (int i = 0; i < 4; i++)
#pragma unroll
        for (int j = 0; j < 4; j++)
#pragma unroll
            for (int c = 0; c < 4; c++) acc[i][j][c] = 0.f;

    const int ar = tid >> 1;
    const int ac = (tid & 1) * 8;
    const int br = tid >> 4;
    const int bc = (tid & 15) * 8;

    const int arow_g = min(brow + ar, M - 1);
    const uint32_t* ag = A + (size_t)arow_g * K + ac;
    const uint32_t* bg = B + (size_t)br * N + bc;

    uint32_t aS[3], bS[3];
#pragma unroll
    for (int s = 0; s < 3; s++) {
        aS[s] = (uint32_t)__cvta_generic_to_shared(smem + s * STAGE_U32 + ar * ASTRIDE + ac);
        bS[s] = (uint32_t)__cvta_generic_to_shared(smem + s * STAGE_U32 + A_TILE_U32 + br * BSTRIDE + bc);
    }

    GEMM_MAINLOOP(K, N)

    // ---- fused epilogue: gelu + 128->2 projection ----
    __syncthreads();
    float* sums = (float*)smem;        // reuse smem (256 floats needed)
    sums[tid] = 0.f;
    __syncthreads();

    const float is2 = 0.70710678118654752f;
#pragma unroll
    for (int mt = 0; mt < 4; mt++) {
        int rl = wm + mt * 16 + gid;          // local rows rl, rl+8
        float s0 = 0.f, s1 = 0.f, s2 = 0.f, s3 = 0.f;
#pragma unroll
        for (int nt = 0; nt < 4; nt++) {
            int c = wn + nt * 8 + 2 * tig;
            float bb0 = bias[c], bb1 = bias[c + 1];
            float v0 = acc[mt][nt][0] + bb0;
            float v1 = acc[mt][nt][1] + bb1;
            float v2 = acc[mt][nt][2] + bb0;
            float v3 = acc[mt][nt][3] + bb1;
            v0 = 0.5f * v0 * (1.0f + erff(v0 * is2));
            v1 = 0.5f * v1 * (1.0f + erff(v1 * is2));
            v2 = 0.5f * v2 * (1.0f + erff(v2 * is2));
            v3 = 0.5f * v3 * (1.0f + erff(v3 * is2));
            float4 w = *(const float4*)(w3 + c * 2);
            s0 += v0 * w.x + v1 * w.z;
            s1 += v0 * w.y + v1 * w.w;
            s2 += v2 * w.x + v3 * w.z;
            s3 += v2 * w.y + v3 * w.w;
        }
        atomicAdd(&sums[rl * 2 + 0], s0);
        atomicAdd(&sums[rl * 2 + 1], s1);
        atomicAdd(&sums[(rl + 8) * 2 + 0], s2);
        atomicAdd(&sums[(rl + 8) * 2 + 1], s3);
    }
    __syncthreads();

    int row = brow + (tid >> 1);
    if (row < M)
        out[(size_t)row * 2 + (tid & 1)] = sums[tid] + b3[tid & 1];
}

// ---------------------------------------------------------------------------
// Layer 1: ReLU + LN → fp32 h1 AND packed A-root (stride 2304)
// ---------------------------------------------------------------------------
__global__ void relu_ln1_kernel(const float* __restrict__ hp,
                                const float* __restrict__ g,
                                const float* __restrict__ b,
                                float* __restrict__ out) {
    int row = blockIdx.x;
    int tid = threadIdx.x;   // 256 == HID
    float v = fmaxf(hp[(size_t)row * HID + tid], 0.0f);

    __shared__ float red[8];
    __shared__ float s_mu, s_rs;

    float s = v;
#pragma unroll
    for (int o = 16; o; o >>= 1) s += __shfl_xor_sync(0xFFFFFFFFu, s, o);
    if ((tid & 31) == 0) red[tid >> 5] = s;
    __syncthreads();
    if (tid == 0) {
        float t = 0.f;
#pragma unroll
        for (int i = 0; i < 8; i++) t += red[i];
        s_mu = t / (float)HID;
    }
    __syncthreads();

    float d = v - s_mu;
    float s2 = d * d;
#pragma unroll
    for (int o = 16; o; o >>= 1) s2 += __shfl_xor_sync(0xFFFFFFFFu, s2, o);
    if ((tid & 31) == 0) red[tid >> 5] = s2;
    __syncthreads();
    if (tid == 0) {
        float t = 0.f;
#pragma unroll
        for (int i = 0; i < 8; i++) t += red[i];
        s_rs = rsqrtf(t / (float)HID + 1e-5f);
    }
    __syncthreads();

    float o = d * s_rs * g[tid] + b[tid];
    out[(size_t)row * HID + tid] = o;                       // fp32 h1 (dense)
    g_A[(size_t)row * 2304 + tid] = bf16_split_pack(o);     // packed A root
}

// Layer 2 variant: packed(resid + LN(relu(hp)))
__global__ void relu_ln_pack_kernel(const float* __restrict__ hp,
                                    const float* __restrict__ g,
                                    const float* __restrict__ b,
                                    uint32_t* __restrict__ outp,
                                    const float* __restrict__ resid) {
    int row = blockIdx.x;
    int tid = threadIdx.x;
    float v = fmaxf(hp[(size_t)row * HID + tid], 0.0f);

    __shared__ float red[8];
    __shared__ float s_mu, s_rs;

    float s = v;
#pragma unroll
    for (int o = 16; o; o >>= 1) s += __shfl_xor_sync(0xFFFFFFFFu, s, o);
    if ((tid & 31) == 0) red[tid >> 5] = s;
    __syncthreads();
    if (tid == 0) {
        float t = 0.f;
#pragma unroll
        for (int i = 0; i < 8; i++) t += red[i];
        s_mu = t / (float)HID;
    }
    __syncthreads();

    float d = v - s_mu;
    float s2 = d * d;
#pragma unroll
    for (int o = 16; o; o >>= 1) s2 += __shfl_xor_sync(0xFFFFFFFFu, s2, o);
    if ((tid & 31) == 0) red[tid >> 5] = s2;
    __syncthreads();
    if (tid == 0) {
        float t = 0.f;
#pragma unroll
        for (int i = 0; i < 8; i++) t += red[i];
        s_rs = rsqrtf(t / (float)HID + 1e-5f);
    }
    __syncthreads();

    float o = d * s_rs * g[tid] + b[tid] + resid[(size_t)row * HID + tid];
    outp[(size_t)row * HID + tid] = bf16_split_pack(o);
}

// ---------------------------------------------------------------------------
// Fused decoder stage 1: Z1[m,c] = packed(gelu(P[u][c] + P[v][256+c] + b1[c]))
// ---------------------------------------------------------------------------
__global__ void decode_fuse_kernel(const int* __restrict__ dec,
                                   const float* __restrict__ b1) {
    int idx = blockIdx.x * blockDim.x + threadIdx.x;
    if (idx >= M_DEC * (HID / 4)) return;
    int m = idx >> 6;
    int j = idx & 63;
    int u = dec[m * 2 + 0];
    int v = dec[m * 2 + 1];
    float4 p = __ldg((const float4*)(g_P + (size_t)u * 512) + j);
    float4 q = __ldg((const float4*)(g_P + (size_t)v * 512 + 256) + j);
    float4 bb = *((const float4*)b1 + j);
    const float is2 = 0.70710678118654752f;
    float zx = p.x + q.x + bb.x; zx = 0.5f * zx * (1.0f + erff(zx * is2));
    float zy = p.y + q.y + bb.y; zy = 0.5f * zy * (1.0f + erff(zy * is2));
    float zz = p.z + q.z + bb.z; zz = 0.5f * zz * (1.0f + erff(zz * is2));
    float zw = p.w + q.w + bb.w; zw = 0.5f * zw * (1.0f + erff(zw * is2));
    uint4 o;
    o.x = bf16_split_pack(zx);
    o.y = bf16_split_pack(zy);
    o.z = bf16_split_pack(zz);
    o.w = bf16_split_pack(zw);
    *((uint4*)(g_Z1 + (size_t)m * HID) + j) = o;
}

// ---------------------------------------------------------------------------
static inline int blocks_for(long long n, int bs) { return (int)((n + bs - 1) / bs); }

extern "C" void kernel_launch(void* const* d_in, const int* in_sizes, int n_in,
                              void* d_out, int out_size) {
    const float* x     = (const float*)d_in[0];
    const int*   ei    = (const int*)  d_in[1];
    const int*   et    = (const int*)  d_in[2];
    const int*   dec   = (const int*)  d_in[3];
    const float* W1    = (const float*)d_in[4];
    const float* root1 = (const float*)d_in[5];
    const float* b1    = (const float*)d_in[6];
    const float* W2    = (const float*)d_in[7];
    const float* root2 = (const float*)d_in[8];
    const float* b2    = (const float*)d_in[9];
    const float* ln1g  = (const float*)d_in[10];
    const float* ln1b  = (const float*)d_in[11];
    const float* ln2g  = (const float*)d_in[12];
    const float* ln2b  = (const float*)d_in[13];
    const float* mw1   = (const float*)d_in[14];
    const float* mb1   = (const float*)d_in[15];
    const float* mw2   = (const float*)d_in[16];
    const float* mb2   = (const float*)d_in[17];
    const float* mw3   = (const float*)d_in[18];
    const float* mb3   = (const float*)d_in[19];
    float* out = (float*)d_out;

    uint32_t *A, *B1p, *B2p, *Bd, *Bw2, *hP, *Z1;
    float *hp, *h1, *P;
    int *deg, *off, *cur;
    cudaGetSymbolAddress((void**)&A,   g_A);
    cudaGetSymbolAddress((void**)&B1p, g_B1);
    cudaGetSymbolAddress((void**)&B2p, g_B2);
    cudaGetSymbolAddress((void**)&Bd,  g_Bd);
    cudaGetSymbolAddress((void**)&Bw2, g_Bw2);
    cudaGetSymbolAddress((void**)&hP,  g_hP);
    cudaGetSymbolAddress((void**)&Z1,  g_Z1);
    cudaGetSymbolAddress((void**)&hp,  g_hp);
    cudaGetSymbolAddress((void**)&h1,  g_h1);
    cudaGetSymbolAddress((void**)&P,   g_P);
    cudaGetSymbolAddress((void**)&deg, g_deg);
    cudaGetSymbolAddress((void**)&off, g_off);
    cudaGetSymbolAddress((void**)&cur, g_cur);

    cudaFuncSetAttribute(gemm_ps_kernel, cudaFuncAttributeMaxDynamicSharedMemorySize, GEMM_SMEM_BYTES);
    cudaFuncSetAttribute(gemm_z2_final_kernel, cudaFuncAttributeMaxDynamicSharedMemorySize, GEMM_SMEM_BYTES);

    // ===================== CSR build =====================
    zero_int_kernel<<<blocks_for(NKEYS / 4, 256), 256>>>(deg, NKEYS / 4);
    hist_kernel<<<blocks_for(E_EDGES, 256), 256>>>(ei, et);
    int nblk = (NKEYS + 1023) / 1024;
    scan1_kernel<<<nblk, 256>>>(deg, off, NKEYS);
    scan2_kernel<<<1, 512>>>(nblk);
    scan3_kernel<<<blocks_for(NKEYS, 256), 256>>>(off, cur, NKEYS);
    fill_kernel<<<blocks_for(E_EDGES, 256), 256>>>(ei, et);

    // ===================== Weight packs + layer-1 root =====================
    copy_feat1_kernel<<<blocks_for(N_NODES * (IN_DIM / 4), 256), 256>>>(x);
    build_B_kernel<<<blocks_for(1152 * HID, 256), 256>>>(root1, W1, IN_DIM, B1p);
    build_B_kernel<<<blocks_for(2304 * HID, 256), 256>>>(root2, W2, HID, B2p);
    build_Bdec_kernel<<<blocks_for(2 * HID * HID, 256), 256>>>(mw1);
    pack_w2_kernel<<<blocks_for(HID * (HID / 2), 256), 256>>>(mw2);

    // ===================== Layer 1 (K = 1152) =====================
    gather_agg_kernel<IN_DIM><<<blocks_for((long long)NKEYS * 32, 256), 256>>>(x);
    {
        dim3 grid(HID / 128, (N_NODES + 127) / 128);
        gemm_ps_kernel<<<grid, 256, GEMM_SMEM_BYTES>>>(A, B1p, hp, b1, N_NODES, HID, 1152, 0);
    }
    relu_ln1_kernel<<<N_NODES, HID>>>(hp, ln1g, ln1b, h1);   // also packs A root

    // ===================== Layer 2 (K = 2304) =====================
    gather_agg_kernel<HID><<<blocks_for((long long)NKEYS * 32, 256), 256>>>(h1);
    {
        dim3 grid(HID / 128, (N_NODES + 127) / 128);
        gemm_ps_kernel<<<grid, 256, GEMM_SMEM_BYTES>>>(A, B2p, hp, b2, N_NODES, HID, 2304, 0);
    }
    relu_ln_pack_kernel<<<N_NODES, HID>>>(hp, ln2g, ln2b, hP, h1);

    // ===================== Decoder =====================
    {
        dim3 gp(4, (N_NODES + 127) / 128);
        gemm_ps_kernel<<<gp, 256, GEMM_SMEM_BYTES>>>(hP, Bd, P, nullptr, N_NODES, 2 * HID, HID, 0);

        decode_fuse_kernel<<<blocks_for((long long)M_DEC * (HID / 4), 256), 256>>>(dec, mb1);

        // Fused: out = gelu(Z1 @ mw2 + mb2) @ mw3 + mb3
        dim3 g2(1, (M_DEC + 127) / 128);
        gemm_z2_final_kernel<<<g2, 256, GEMM_SMEM_BYTES>>>(Z1, Bw2, mb2, mw3, mb3, out, M_DEC, HID);
    }
}

// round 17
// speedup vs baseline: 1.0767x; 1.0767x over previous
#include <cuda_runtime.h>
#include <cuda_bf16.h>
#include <cstdint>
#include <cstddef>

#define N_NODES 50000
#define NUM_REL 8
#define IN_DIM  128
#define HID     256
#define E_EDGES 1600000
#define M_DEC   200000
#define NKEYS   (N_NODES * NUM_REL)      // 400000

// ---------------------------------------------------------------------------
// Device scratch. Packed format ("ps32"): one uint32 per element =
// (bf16(lo) << 16) | bf16(hi), hi = bf16(x), lo = bf16(x - float(hi)).
// ---------------------------------------------------------------------------
__device__ int      g_deg[NKEYS];
__device__ int      g_off[NKEYS];
__device__ int      g_cur[NKEYS];
__device__ int      g_srcs[E_EDGES];
__device__ int      g_bsums[512];
__device__ uint32_t g_A[(size_t)N_NODES * (HID + NUM_REL * HID)];   // packed, N x 2304 (layer1: N x 1152)
__device__ uint32_t g_B1[1152 * HID];            // layer1 weights [k][n] packed
__device__ uint32_t g_B2[2304 * HID];            // layer2 weights [k][n] packed
__device__ uint32_t g_Bd[HID * 2 * HID];         // decoder W1' (256 x 512) packed
__device__ uint32_t g_Bw2[HID * (HID / 2)];      // decoder W2  (256 x 128) packed
__device__ float    g_hp[(size_t)N_NODES * HID];
__device__ float    g_h1[(size_t)N_NODES * HID];                    // fp32 h1 (dense, L2-hot)
__device__ uint32_t g_hP[(size_t)N_NODES * HID];                    // packed final h
__device__ float    g_P [(size_t)N_NODES * 2 * HID];                // 50000 x 512
__device__ uint32_t g_Z1[(size_t)M_DEC * HID];                      // packed

// ---------------------------------------------------------------------------
__device__ __forceinline__ uint32_t bf16_split_pack(float x) {
    __nv_bfloat16 h = __float2bfloat16(x);
    float hf = __bfloat162float(h);
    __nv_bfloat16 l = __float2bfloat16(x - hf);
    return ((uint32_t)__bfloat16_as_ushort(l) << 16) | (uint32_t)__bfloat16_as_ushort(h);
}

__global__ void zero_int_kernel(int* __restrict__ p, int n4) {
    int i = blockIdx.x * blockDim.x + threadIdx.x;
    if (i < n4) ((int4*)p)[i] = make_int4(0, 0, 0, 0);
}

// ---------------------------------------------------------------------------
// CSR build over keys (dst*8 + rel)
// ---------------------------------------------------------------------------
__global__ void hist_kernel(const int* __restrict__ ei, const int* __restrict__ et) {
    int e = blockIdx.x * blockDim.x + threadIdx.x;
    if (e >= E_EDGES) return;
    int key = ei[E_EDGES + e] * NUM_REL + et[e];
    atomicAdd(&g_deg[key], 1);
}

__global__ void scan1_kernel(const int* __restrict__ in, int* __restrict__ out, int n) {
    __shared__ int s[256];
    int t = threadIdx.x;
    int base = blockIdx.x * 1024 + t * 4;
    int v0 = 0, v1 = 0, v2 = 0, v3 = 0;
    if (base + 0 < n) v0 = in[base + 0];
    if (base + 1 < n) v1 = in[base + 1];
    if (base + 2 < n) v2 = in[base + 2];
    if (base + 3 < n) v3 = in[base + 3];
    int tsum = v0 + v1 + v2 + v3;
    s[t] = tsum;
    __syncthreads();
    for (int o = 1; o < 256; o <<= 1) {
        int x = (t >= o) ? s[t - o] : 0;
        __syncthreads();
        s[t] += x;
        __syncthreads();
    }
    int excl = s[t] - tsum;
    if (t == 255) g_bsums[blockIdx.x] = s[255];
    if (base + 0 < n) out[base + 0] = excl;
    if (base + 1 < n) out[base + 1] = excl + v0;
    if (base + 2 < n) out[base + 2] = excl + v0 + v1;
    if (base + 3 < n) out[base + 3] = excl + v0 + v1 + v2;
}

__global__ void scan2_kernel(int nb) {
    __shared__ int s[512];
    int t = threadIdx.x;
    int v = (t < nb) ? g_bsums[t] : 0;
    s[t] = v;
    __syncthreads();
    for (int o = 1; o < 512; o <<= 1) {
        int x = (t >= o) ? s[t - o] : 0;
        __syncthreads();
        s[t] += x;
        __syncthreads();
    }
    if (t < nb) g_bsums[t] = s[t] - v;   // exclusive
}

__global__ void scan3_kernel(int* __restrict__ off, int* __restrict__ cur, int n) {
    int i = blockIdx.x * blockDim.x + threadIdx.x;
    if (i >= n) return;
    int o = off[i] + g_bsums[i >> 10];
    off[i] = o;
    cur[i] = o;
}

__global__ void fill_kernel(const int* __restrict__ ei, const int* __restrict__ et) {
    int e = blockIdx.x * blockDim.x + threadIdx.x;
    if (e >= E_EDGES) return;
    int key = ei[E_EDGES + e] * NUM_REL + et[e];
    int p = atomicAdd(&g_cur[key], 1);
    g_srcs[p] = ei[e];
}

// ---------------------------------------------------------------------------
// Gather-reduce aggregation (one warp per (node, rel) key) → packed mean into
// g_A[n, (1+r)*DIN : (2+r)*DIN].  fp32 inputs (precision floor: ps32 or fp32).
// ---------------------------------------------------------------------------
template <int DIN>
__global__ void gather_agg_kernel(const float* __restrict__ feat) {
    const int K = DIN * (NUM_REL + 1);
    int w = (blockIdx.x * blockDim.x + threadIdx.x) >> 5;
    int lane = threadIdx.x & 31;
    if (w >= NKEYS) return;
    int n = w >> 3;
    int r = w & 7;
    int off = g_off[w];
    int cnt = g_deg[w];

    float4 a0 = make_float4(0.f, 0.f, 0.f, 0.f);
    float4 a1 = make_float4(0.f, 0.f, 0.f, 0.f);

    int i = 0;
    for (; i + 2 <= cnt; i += 2) {
        int s0 = g_srcs[off + i];
        int s1 = g_srcs[off + i + 1];
        const float4* p0 = (const float4*)(feat + (size_t)s0 * DIN) + lane;
        const float4* p1 = (const float4*)(feat + (size_t)s1 * DIN) + lane;
        float4 v0 = __ldg(p0);
        float4 v1 = __ldg(p1);
        float4 u0, u1;
        if (DIN == 256) { u0 = __ldg(p0 + 32); u1 = __ldg(p1 + 32); }
        a0.x += v0.x + v1.x; a0.y += v0.y + v1.y;
        a0.z += v0.z + v1.z; a0.w += v0.w + v1.w;
        if (DIN == 256) {
            a1.x += u0.x + u1.x; a1.y += u0.y + u1.y;
            a1.z += u0.z + u1.z; a1.w += u0.w + u1.w;
        }
    }
    if (i < cnt) {
        int s0 = g_srcs[off + i];
        const float4* p0 = (const float4*)(feat + (size_t)s0 * DIN) + lane;
        float4 v0 = __ldg(p0);
        a0.x += v0.x; a0.y += v0.y; a0.z += v0.z; a0.w += v0.w;
        if (DIN == 256) {
            float4 u0 = __ldg(p0 + 32);
            a1.x += u0.x; a1.y += u0.y; a1.z += u0.z; a1.w += u0.w;
        }
    }

    float sc = 1.0f / fmaxf((float)cnt, 1.0f);
    uint4 o0;
    o0.x = bf16_split_pack(a0.x * sc);
    o0.y = bf16_split_pack(a0.y * sc);
    o0.z = bf16_split_pack(a0.z * sc);
    o0.w = bf16_split_pack(a0.w * sc);
    uint4* dst = (uint4*)(g_A + (size_t)n * K + (1 + r) * DIN) + lane;
    *dst = o0;
    if (DIN == 256) {
        uint4 o1;
        o1.x = bf16_split_pack(a1.x * sc);
        o1.y = bf16_split_pack(a1.y * sc);
        o1.z = bf16_split_pack(a1.z * sc);
        o1.w = bf16_split_pack(a1.w * sc);
        *(dst + 32) = o1;
    }
}

// Layer-1 root copy: x packed into A[:, 0:128] (stride 1152)
__global__ void copy_feat1_kernel(const float* __restrict__ feat) {
    const int K = 1152;
    const int L = IN_DIM / 4;
    int idx = blockIdx.x * blockDim.x + threadIdx.x;
    if (idx >= N_NODES * L) return;
    int n = idx / L;
    int j = idx % L;
    float4 v = *((const float4*)(feat + (size_t)n * IN_DIM) + j);
    uint4 o;
    o.x = bf16_split_pack(v.x);
    o.y = bf16_split_pack(v.y);
    o.z = bf16_split_pack(v.z);
    o.w = bf16_split_pack(v.w);
    *((uint4*)(g_A + (size_t)n * K) + j) = o;
}

// ---------------------------------------------------------------------------
// Weight builders ([k][n] packed), each to its own buffer
// ---------------------------------------------------------------------------
__global__ void build_B_kernel(const float* __restrict__ root,
                               const float* __restrict__ W, int Kin,
                               uint32_t* __restrict__ out) {
    int total = Kin * (NUM_REL + 1) * HID;
    int idx = blockIdx.x * blockDim.x + threadIdx.x;
    if (idx >= total) return;
    int rootN = Kin * HID;
    float v = (idx < rootN) ? root[idx] : W[idx - rootN];
    out[idx] = bf16_split_pack(v);
}

// Decoder B' (256 x 512): cols 0..255 = mw1_top, 256..511 = mw1_bot
__global__ void build_Bdec_kernel(const float* __restrict__ mw1) {
    int idx = blockIdx.x * blockDim.x + threadIdx.x;   // 256*512
    if (idx >= HID * 2 * HID) return;
    int k = idx >> 9;
    int n = idx & 511;
    float v = (n < HID) ? mw1[k * HID + n] : mw1[(HID + k) * HID + (n - HID)];
    g_Bd[idx] = bf16_split_pack(v);
}

__global__ void pack_w2_kernel(const float* __restrict__ mw2) {
    int idx = blockIdx.x * blockDim.x + threadIdx.x;
    if (idx >= HID * (HID / 2)) return;
    g_Bw2[idx] = bf16_split_pack(mw2[idx]);
}

// ---------------------------------------------------------------------------
// Packed-split BF16 GEMM, 3-term compensation, cp.async 2-stage pipeline (R6).
// ---------------------------------------------------------------------------
#define ASTRIDE 20
#define BSTRIDE 132

__device__ __forceinline__ void cp16(uint32_t smem, const void* g) {
    asm volatile("cp.async.cg.shared.global [%0], [%1], 16;" :: "r"(smem), "l"(g));
}

#define MMA_BF16(d, a, b)                                                     \
    asm volatile("mma.sync.aligned.m16n8k16.row.col.f32.bf16.bf16.f32 "       \
                 "{%0,%1,%2,%3}, {%4,%5,%6,%7}, {%8,%9}, {%0,%1,%2,%3};"      \
                 : "+f"(d[0]), "+f"(d[1]), "+f"(d[2]), "+f"(d[3])             \
                 : "r"(a[0]), "r"(a[1]), "r"(a[2]), "r"(a[3]),                \
                   "r"(b[0]), "r"(b[1]))

__global__ __launch_bounds__(256, 2)
void gemm_ps_kernel(const uint32_t* __restrict__ A, const uint32_t* __restrict__ B,
                    float* __restrict__ C, const float* __restrict__ bias,
                    int M, int N, int K, int act) {
    __shared__ uint32_t As[2][128 * ASTRIDE];
    __shared__ uint32_t Bs[2][16 * BSTRIDE];

    const int tid  = threadIdx.x;
    const int warp = tid >> 5, lane = tid & 31;
    const int gid  = lane >> 2, tig = lane & 3;
    const int wm   = (warp & 1) * 64, wn = (warp >> 1) * 32;
    const int brow = blockIdx.y * 128, bcol = blockIdx.x * 128;

    float acc[4][4][4];
#pragma unroll
    for (int i = 0; i < 4; i++)
#pragma unroll
        for (int j = 0; j < 4; j++)
#pragma unroll
            for (int c = 0; c < 4; c++) acc[i][j][c] = 0.f;

    const int ar = tid >> 1;
    const int ac = (tid & 1) * 8;
    const int br = tid >> 4;
    const int bc = (tid & 15) * 8;

    const int arow_g = min(brow + ar, M - 1);
    const uint32_t* ag = A + (size_t)arow_g * K + ac;
    const uint32_t* bg = B + (size_t)br * N + bcol + bc;

    const uint32_t a_sm0 = (uint32_t)__cvta_generic_to_shared(&As[0][ar * ASTRIDE + ac]);
    const uint32_t a_sm1 = (uint32_t)__cvta_generic_to_shared(&As[1][ar * ASTRIDE + ac]);
    const uint32_t b_sm0 = (uint32_t)__cvta_generic_to_shared(&Bs[0][br * BSTRIDE + bc]);
    const uint32_t b_sm1 = (uint32_t)__cvta_generic_to_shared(&Bs[1][br * BSTRIDE + bc]);

    const int ntiles = K >> 4;

    cp16(a_sm0,      ag);
    cp16(a_sm0 + 16, ag + 4);
    cp16(b_sm0,      bg);
    cp16(b_sm0 + 16, bg + 4);
    asm volatile("cp.async.commit_group;");

    for (int t = 0; t < ntiles; t++) {
        if (t + 1 < ntiles) {
            int k0 = (t + 1) << 4;
            uint32_t asm_ = ((t + 1) & 1) ? a_sm1 : a_sm0;
            uint32_t bsm_ = ((t + 1) & 1) ? b_sm1 : b_sm0;
            cp16(asm_,      ag + k0);
            cp16(asm_ + 16, ag + k0 + 4);
            cp16(bsm_,      bg + (size_t)k0 * N);
            cp16(bsm_ + 16, bg + (size_t)k0 * N + 4);
            asm volatile("cp.async.commit_group;");
            asm volatile("cp.async.wait_group 1;");
        } else {
            asm volatile("cp.async.wait_group 0;");
        }
        __syncthreads();

        const uint32_t* as = As[t & 1];
        const uint32_t* bs = Bs[t & 1];

        uint32_t bh[4][2], bl[4][2];
#pragma unroll
        for (int nt = 0; nt < 4; nt++) {
            int n = wn + nt * 8 + gid;
            uint32_t r0 = bs[(tig * 2 + 0) * BSTRIDE + n];
            uint32_t r1 = bs[(tig * 2 + 1) * BSTRIDE + n];
            uint32_t r2 = bs[(tig * 2 + 8) * BSTRIDE + n];
            uint32_t r3 = bs[(tig * 2 + 9) * BSTRIDE + n];
            bh[nt][0] = __byte_perm(r0, r1, 0x5410);
            bh[nt][1] = __byte_perm(r2, r3, 0x5410);
            bl[nt][0] = __byte_perm(r0, r1, 0x7632);
            bl[nt][1] = __byte_perm(r2, r3, 0x7632);
        }
#pragma unroll
        for (int mt = 0; mt < 4; mt++) {
            int m0 = wm + mt * 16 + gid;
            uint2 p0 = *(const uint2*)&as[m0 * ASTRIDE + tig * 2];
            uint2 p1 = *(const uint2*)&as[(m0 + 8) * ASTRIDE + tig * 2];
            uint2 p2 = *(const uint2*)&as[m0 * ASTRIDE + tig * 2 + 8];
            uint2 p3 = *(const uint2*)&as[(m0 + 8) * ASTRIDE + tig * 2 + 8];
            uint32_t ah[4] = {__byte_perm(p0.x, p0.y, 0x5410), __byte_perm(p1.x, p1.y, 0x5410),
                              __byte_perm(p2.x, p2.y, 0x5410), __byte_perm(p3.x, p3.y, 0x5410)};
            uint32_t al[4] = {__byte_perm(p0.x, p0.y, 0x7632), __byte_perm(p1.x, p1.y, 0x7632),
                              __byte_perm(p2.x, p2.y, 0x7632), __byte_perm(p3.x, p3.y, 0x7632)};
#pragma unroll
            for (int nt = 0; nt < 4; nt++) {
                MMA_BF16(acc[mt][nt], ah, bh[nt]);
                MMA_BF16(acc[mt][nt], ah, bl[nt]);
                MMA_BF16(acc[mt][nt], al, bh[nt]);
            }
        }
        __syncthreads();
    }

#pragma unroll
    for (int mt = 0; mt < 4; mt++) {
        int r0 = brow + wm + mt * 16 + gid;
#pragma unroll
        for (int nt = 0; nt < 4; nt++) {
            int c = bcol + wn + nt * 8 + 2 * tig;
            float bb0 = bias ? bias[c] : 0.f;
            float bb1 = bias ? bias[c + 1] : 0.f;
            float v0 = acc[mt][nt][0] + bb0;
            float v1 = acc[mt][nt][1] + bb1;
            float v2 = acc[mt][nt][2] + bb0;
            float v3 = acc[mt][nt][3] + bb1;
            if (act == 1) {
                const float is2 = 0.70710678118654752f;
                v0 = 0.5f * v0 * (1.0f + erff(v0 * is2));
                v1 = 0.5f * v1 * (1.0f + erff(v1 * is2));
                v2 = 0.5f * v2 * (1.0f + erff(v2 * is2));
                v3 = 0.5f * v3 * (1.0f + erff(v3 * is2));
            }
            if (r0 < M)
                *(float2*)(C + (size_t)r0 * N + c) = make_float2(v0, v1);
            if (r0 + 8 < M)
                *(float2*)(C + (size_t)(r0 + 8) * N + c) = make_float2(v2, v3);
        }
    }
}

// ---------------------------------------------------------------------------
// Z2 GEMM with FUSED final projection (2-stage, static smem, R14):
//   out[m, 0:2] = gelu(Z1[m,:] @ W2 + b2) @ w3 + b3
// ---------------------------------------------------------------------------
__global__ __launch_bounds__(256, 2)
void gemm_z2_final_kernel(const uint32_t* __restrict__ A, const uint32_t* __restrict__ B,
                          const float* __restrict__ bias,
                          const float* __restrict__ w3, const float* __restrict__ b3,
                          float* __restrict__ out, int M, int K) {
    const int N = 128;
    __shared__ uint32_t As[2][128 * ASTRIDE];
    __shared__ uint32_t Bs[2][16 * BSTRIDE];

    const int tid  = threadIdx.x;
    const int warp = tid >> 5, lane = tid & 31;
    const int gid  = lane >> 2, tig = lane & 3;
    const int wm   = (warp & 1) * 64, wn = (warp >> 1) * 32;
    const int brow = blockIdx.y * 128;

    float acc[4][4][4];
#pragma unroll
    for (int i = 0; i < 4; i++)
#pragma unroll
        for (int j = 0; j < 4; j++)
#pragma unroll
            for (int c = 0; c < 4; c++) acc[i][j][c] = 0.f;

    const int ar = tid >> 1;
    const int ac = (tid & 1) * 8;
    const int br = tid >> 4;
    const int bc = (tid & 15) * 8;

    const int arow_g = min(brow + ar, M - 1);
    const uint32_t* ag = A + (size_t)arow_g * K + ac;
    const uint32_t* bg = B + (size_t)br * N + bc;

    const uint32_t a_sm0 = (uint32_t)__cvta_generic_to_shared(&As[0][ar * ASTRIDE + ac]);
    const uint32_t a_sm1 = (uint32_t)__cvta_generic_to_shared(&As[1][ar * ASTRIDE + ac]);
    const uint32_t b_sm0 = (uint32_t)__cvta_generic_to_shared(&Bs[0][br * BSTRIDE + bc]);
    const uint32_t b_sm1 = (uint32_t)__cvta_generic_to_shared(&Bs[1][br * BSTRIDE + bc]);

    const int ntiles = K >> 4;

    cp16(a_sm0,      ag);
    cp16(a_sm0 + 16, ag + 4);
    cp16(b_sm0,      bg);
    cp16(b_sm0 + 16, bg + 4);
    asm volatile("cp.async.commit_group;");

    for (int t = 0; t < ntiles; t++) {
        if (t + 1 < ntiles) {
            int k0 = (t + 1) << 4;
            uint32_t asm_ = ((t + 1) & 1) ? a_sm1 : a_sm0;
            uint32_t bsm_ = ((t + 1) & 1) ? b_sm1 : b_sm0;
            cp16(asm_,      ag + k0);
            cp16(asm_ + 16, ag + k0 + 4);
            cp16(bsm_,      bg + (size_t)k0 * N);
            cp16(bsm_ + 16, bg + (size_t)k0 * N + 4);
            asm volatile("cp.async.commit_group;");
            asm volatile("cp.async.wait_group 1;");
        } else {
            asm volatile("cp.async.wait_group 0;");
        }
        __syncthreads();

        const uint32_t* as = As[t & 1];
        const uint32_t* bs = Bs[t & 1];

        uint32_t bh[4][2], bl[4][2];
#pragma unroll
        for (int nt = 0; nt < 4; nt++) {
            int n = wn + nt * 8 + gid;
            uint32_t r0 = bs[(tig * 2 + 0) * BSTRIDE + n];
            uint32_t r1 = bs[(tig * 2 + 1) * BSTRIDE + n];
            uint32_t r2 = bs[(tig * 2 + 8) * BSTRIDE + n];
            uint32_t r3 = bs[(tig * 2 + 9) * BSTRIDE + n];
            bh[nt][0] = __byte_perm(r0, r1, 0x5410);
            bh[nt][1] = __byte_perm(r2, r3, 0x5410);
            bl[nt][0] = __byte_perm(r0, r1, 0x7632);
            bl[nt][1] = __byte_perm(r2, r3, 0x7632);
        }
#pragma unroll
        for (int mt = 0; mt < 4; mt++) {
            int m0 = wm + mt * 16 + gid;
            uint2 p0 = *(const uint2*)&as[m0 * ASTRIDE + tig * 2];
            uint2 p1 = *(const uint2*)&as[(m0 + 8) * ASTRIDE + tig * 2];
            uint2 p2 = *(const uint2*)&as[m0 * ASTRIDE + tig * 2 + 8];
            uint2 p3 = *(const uint2*)&as[(m0 + 8) * ASTRIDE + tig * 2 + 8];
            uint32_t ah[4] = {__byte_perm(p0.x, p0.y, 0x5410), __byte_perm(p1.x, p1.y, 0x5410),
                              __byte_perm(p2.x, p2.y, 0x5410), __byte_perm(p3.x, p3.y, 0x5410)};
            uint32_t al[4] = {__byte_perm(p0.x, p0.y, 0x7632), __byte_perm(p1.x, p1.y, 0x7632),
                              __byte_perm(p2.x, p2.y, 0x7632), __byte_perm(p3.x, p3.y, 0x7632)};
#pragma unroll
            for (int nt = 0; nt < 4; nt++) {
                MMA_BF16(acc[mt][nt], ah, bh[nt]);
                MMA_BF16(acc[mt][nt], ah, bl[nt]);
                MMA_BF16(acc[mt][nt], al, bh[nt]);
            }
        }
        __syncthreads();
    }

    // ---- fused epilogue: gelu + 128->2 projection ----
    float* sums = (float*)As;          // reuse A-stage smem (256 floats needed)
    sums[tid] = 0.f;
    __syncthreads();

    const float is2 = 0.70710678118654752f;
#pragma unroll
    for (int mt = 0; mt < 4; mt++) {
        int rl = wm + mt * 16 + gid;          // local rows rl, rl+8
        float s0 = 0.f, s1 = 0.f, s2 = 0.f, s3 = 0.f;
#pragma unroll
        for (int nt = 0; nt < 4; nt++) {
            int c = wn + nt * 8 + 2 * tig;
            float bb0 = bias[c], bb1 = bias[c + 1];
            float v0 = acc[mt][nt][0] + bb0;
            float v1 = acc[mt][nt][1] + bb1;
            float v2 = acc[mt][nt][2] + bb0;
            float v3 = acc[mt][nt][3] + bb1;
            v0 = 0.5f * v0 * (1.0f + erff(v0 * is2));
            v1 = 0.5f * v1 * (1.0f + erff(v1 * is2));
            v2 = 0.5f * v2 * (1.0f + erff(v2 * is2));
            v3 = 0.5f * v3 * (1.0f + erff(v3 * is2));
            float4 w = *(const float4*)(w3 + c * 2);   // w3[c][0..1], w3[c+1][0..1]
            s0 += v0 * w.x + v1 * w.z;
            s1 += v0 * w.y + v1 * w.w;
            s2 += v2 * w.x + v3 * w.z;
            s3 += v2 * w.y + v3 * w.w;
        }
        atomicAdd(&sums[rl * 2 + 0], s0);
        atomicAdd(&sums[rl * 2 + 1], s1);
        atomicAdd(&sums[(rl + 8) * 2 + 0], s2);
        atomicAdd(&sums[(rl + 8) * 2 + 1], s3);
    }
    __syncthreads();

    int row = brow + (tid >> 1);
    if (row < M)
        out[(size_t)row * 2 + (tid & 1)] = sums[tid] + b3[tid & 1];
}

// ---------------------------------------------------------------------------
// Warp-per-row ReLU + LayerNorm (no block barriers, no smem).
// Lane covers elements [lane*8, lane*8+8).  grid: N_NODES/8 blocks of 256.
// Layer 1: writes fp32 h1 AND packed A-root (stride 2304).
// ---------------------------------------------------------------------------
__global__ void relu_ln1_kernel(const float* __restrict__ hp,
                                const float* __restrict__ g,
                                const float* __restrict__ b,
                                float* __restrict__ out) {
    int w = (blockIdx.x * blockDim.x + threadIdx.x) >> 5;
    int lane = threadIdx.x & 31;
    if (w >= N_NODES) return;
    const float* row = hp + (size_t)w * HID + lane * 8;
    float4 v0 = *(const float4*)row;
    float4 v1 = *(const float4*)(row + 4);
    float e[8] = {fmaxf(v0.x, 0.f), fmaxf(v0.y, 0.f), fmaxf(v0.z, 0.f), fmaxf(v0.w, 0.f),
                  fmaxf(v1.x, 0.f), fmaxf(v1.y, 0.f), fmaxf(v1.z, 0.f), fmaxf(v1.w, 0.f)};

    float s = 0.f;
#pragma unroll
    for (int i = 0; i < 8; i++) s += e[i];
#pragma unroll
    for (int o = 16; o; o >>= 1) s += __shfl_xor_sync(0xFFFFFFFFu, s, o);
    float mu = s / (float)HID;

    float s2 = 0.f;
#pragma unroll
    for (int i = 0; i < 8; i++) { float d = e[i] - mu; s2 += d * d; }
#pragma unroll
    for (int o = 16; o; o >>= 1) s2 += __shfl_xor_sync(0xFFFFFFFFu, s2, o);
    float rs = rsqrtf(s2 / (float)HID + 1e-5f);

    float4 g0 = *(const float4*)(g + lane * 8);
    float4 g1 = *(const float4*)(g + lane * 8 + 4);
    float4 b0 = *(const float4*)(b + lane * 8);
    float4 b1v = *(const float4*)(b + lane * 8 + 4);
    float gg[8] = {g0.x, g0.y, g0.z, g0.w, g1.x, g1.y, g1.z, g1.w};
    float bb[8] = {b0.x, b0.y, b0.z, b0.w, b1v.x, b1v.y, b1v.z, b1v.w};

    float* op = out + (size_t)w * HID + lane * 8;
    uint32_t* ap = g_A + (size_t)w * 2304 + lane * 8;
    float4 o0, o1;
    uint4 q0, q1;
    float t0 = (e[0] - mu) * rs * gg[0] + bb[0];
    float t1 = (e[1] - mu) * rs * gg[1] + bb[1];
    float t2 = (e[2] - mu) * rs * gg[2] + bb[2];
    float t3 = (e[3] - mu) * rs * gg[3] + bb[3];
    float t4 = (e[4] - mu) * rs * gg[4] + bb[4];
    float t5 = (e[5] - mu) * rs * gg[5] + bb[5];
    float t6 = (e[6] - mu) * rs * gg[6] + bb[6];
    float t7 = (e[7] - mu) * rs * gg[7] + bb[7];
    o0 = make_float4(t0, t1, t2, t3);
    o1 = make_float4(t4, t5, t6, t7);
    q0.x = bf16_split_pack(t0); q0.y = bf16_split_pack(t1);
    q0.z = bf16_split_pack(t2); q0.w = bf16_split_pack(t3);
    q1.x = bf16_split_pack(t4); q1.y = bf16_split_pack(t5);
    q1.z = bf16_split_pack(t6); q1.w = bf16_split_pack(t7);
    *(float4*)op = o0;
    *(float4*)(op + 4) = o1;
    *(uint4*)ap = q0;
    *(uint4*)(ap + 4) = q1;
}

// Layer 2: packed(resid + LN(relu(hp))), warp-per-row
__global__ void relu_ln2_kernel(const float* __restrict__ hp,
                                const float* __restrict__ g,
                                const float* __restrict__ b,
                                uint32_t* __restrict__ outp,
                                const float* __restrict__ resid) {
    int w = (blockIdx.x * blockDim.x + threadIdx.x) >> 5;
    int lane = threadIdx.x & 31;
    if (w >= N_NODES) return;
    const float* row = hp + (size_t)w * HID + lane * 8;
    float4 v0 = *(const float4*)row;
    float4 v1 = *(const float4*)(row + 4);
    float e[8] = {fmaxf(v0.x, 0.f), fmaxf(v0.y, 0.f), fmaxf(v0.z, 0.f), fmaxf(v0.w, 0.f),
                  fmaxf(v1.x, 0.f), fmaxf(v1.y, 0.f), fmaxf(v1.z, 0.f), fmaxf(v1.w, 0.f)};

    float s = 0.f;
#pragma unroll
    for (int i = 0; i < 8; i++) s += e[i];
#pragma unroll
    for (int o = 16; o; o >>= 1) s += __shfl_xor_sync(0xFFFFFFFFu, s, o);
    float mu = s / (float)HID;

    float s2 = 0.f;
#pragma unroll
    for (int i = 0; i < 8; i++) { float d = e[i] - mu; s2 += d * d; }
#pragma unroll
    for (int o = 16; o; o >>= 1) s2 += __shfl_xor_sync(0xFFFFFFFFu, s2, o);
    float rs = rsqrtf(s2 / (float)HID + 1e-5f);

    float4 g0 = *(const float4*)(g + lane * 8);
    float4 g1 = *(const float4*)(g + lane * 8 + 4);
    float4 b0 = *(const float4*)(b + lane * 8);
    float4 b1v = *(const float4*)(b + lane * 8 + 4);
    float gg[8] = {g0.x, g0.y, g0.z, g0.w, g1.x, g1.y, g1.z, g1.w};
    float bb[8] = {b0.x, b0.y, b0.z, b0.w, b1v.x, b1v.y, b1v.z, b1v.w};

    const float* rp = resid + (size_t)w * HID + lane * 8;
    float4 r0 = *(const float4*)rp;
    float4 r1 = *(const float4*)(rp + 4);
    float rr[8] = {r0.x, r0.y, r0.z, r0.w, r1.x, r1.y, r1.z, r1.w};

    uint32_t* op = outp + (size_t)w * HID + lane * 8;
    uint4 q0, q1;
    q0.x = bf16_split_pack((e[0] - mu) * rs * gg[0] + bb[0] + rr[0]);
    q0.y = bf16_split_pack((e[1] - mu) * rs * gg[1] + bb[1] + rr[1]);
    q0.z = bf16_split_pack((e[2] - mu) * rs * gg[2] + bb[2] + rr[2]);
    q0.w = bf16_split_pack((e[3] - mu) * rs * gg[3] + bb[3] + rr[3]);
    q1.x = bf16_split_pack((e[4] - mu) * rs * gg[4] + bb[4] + rr[4]);
    q1.y = bf16_split_pack((e[5] - mu) * rs * gg[5] + bb[5] + rr[5]);
    q1.z = bf16_split_pack((e[6] - mu) * rs * gg[6] + bb[6] + rr[6]);
    q1.w = bf16_split_pack((e[7] - mu) * rs * gg[7] + bb[7] + rr[7]);
    *(uint4*)op = q0;
    *(uint4*)(op + 4) = q1;
}

// ---------------------------------------------------------------------------
// Fused decoder stage 1: Z1[m,c] = packed(gelu(P[u][c] + P[v][256+c] + b1[c]))
// ---------------------------------------------------------------------------
__global__ void decode_fuse_kernel(const int* __restrict__ dec,
                                   const float* __restrict__ b1) {
    int idx = blockIdx.x * blockDim.x + threadIdx.x;
    if (idx >= M_DEC * (HID / 4)) return;
    int m = idx >> 6;
    int j = idx & 63;
    int u = dec[m * 2 + 0];
    int v = dec[m * 2 + 1];
    float4 p = __ldg((const float4*)(g_P + (size_t)u * 512) + j);
    float4 q = __ldg((const float4*)(g_P + (size_t)v * 512 + 256) + j);
    float4 bb = *((const float4*)b1 + j);
    const float is2 = 0.70710678118654752f;
    float zx = p.x + q.x + bb.x; zx = 0.5f * zx * (1.0f + erff(zx * is2));
    float zy = p.y + q.y + bb.y; zy = 0.5f * zy * (1.0f + erff(zy * is2));
    float zz = p.z + q.z + bb.z; zz = 0.5f * zz * (1.0f + erff(zz * is2));
    float zw = p.w + q.w + bb.w; zw = 0.5f * zw * (1.0f + erff(zw * is2));
    uint4 o;
    o.x = bf16_split_pack(zx);
    o.y = bf16_split_pack(zy);
    o.z = bf16_split_pack(zz);
    o.w = bf16_split_pack(zw);
    *((uint4*)(g_Z1 + (size_t)m * HID) + j) = o;
}

// ---------------------------------------------------------------------------
static inline int blocks_for(long long n, int bs) { return (int)((n + bs - 1) / bs); }

extern "C" void kernel_launch(void* const* d_in, const int* in_sizes, int n_in,
                              void* d_out, int out_size) {
    const float* x     = (const float*)d_in[0];
    const int*   ei    = (const int*)  d_in[1];
    const int*   et    = (const int*)  d_in[2];
    const int*   dec   = (const int*)  d_in[3];
    const float* W1    = (const float*)d_in[4];
    const float* root1 = (const float*)d_in[5];
    const float* b1    = (const float*)d_in[6];
    const float* W2    = (const float*)d_in[7];
    const float* root2 = (const float*)d_in[8];
    const float* b2    = (const float*)d_in[9];
    const float* ln1g  = (const float*)d_in[10];
    const float* ln1b  = (const float*)d_in[11];
    const float* ln2g  = (const float*)d_in[12];
    const float* ln2b  = (const float*)d_in[13];
    const float* mw1   = (const float*)d_in[14];
    const float* mb1   = (const float*)d_in[15];
    const float* mw2   = (const float*)d_in[16];
    const float* mb2   = (const float*)d_in[17];
    const float* mw3   = (const float*)d_in[18];
    const float* mb3   = (const float*)d_in[19];
    float* out = (float*)d_out;

    uint32_t *A, *B1p, *B2p, *Bd, *Bw2, *hP, *Z1;
    float *hp, *h1, *P;
    int *deg, *off, *cur;
    cudaGetSymbolAddress((void**)&A,   g_A);
    cudaGetSymbolAddress((void**)&B1p, g_B1);
    cudaGetSymbolAddress((void**)&B2p, g_B2);
    cudaGetSymbolAddress((void**)&Bd,  g_Bd);
    cudaGetSymbolAddress((void**)&Bw2, g_Bw2);
    cudaGetSymbolAddress((void**)&hP,  g_hP);
    cudaGetSymbolAddress((void**)&Z1,  g_Z1);
    cudaGetSymbolAddress((void**)&hp,  g_hp);
    cudaGetSymbolAddress((void**)&h1,  g_h1);
    cudaGetSymbolAddress((void**)&P,   g_P);
    cudaGetSymbolAddress((void**)&deg, g_deg);
    cudaGetSymbolAddress((void**)&off, g_off);
    cudaGetSymbolAddress((void**)&cur, g_cur);

    // ===================== CSR build =====================
    zero_int_kernel<<<blocks_for(NKEYS / 4, 256), 256>>>(deg, NKEYS / 4);
    hist_kernel<<<blocks_for(E_EDGES, 256), 256>>>(ei, et);
    int nblk = (NKEYS + 1023) / 1024;
    scan1_kernel<<<nblk, 256>>>(deg, off, NKEYS);
    scan2_kernel<<<1, 512>>>(nblk);
    scan3_kernel<<<blocks_for(NKEYS, 256), 256>>>(off, cur, NKEYS);
    fill_kernel<<<blocks_for(E_EDGES, 256), 256>>>(ei, et);

    // ===================== Weight packs + layer-1 root =====================
    copy_feat1_kernel<<<blocks_for(N_NODES * (IN_DIM / 4), 256), 256>>>(x);
    build_B_kernel<<<blocks_for(1152 * HID, 256), 256>>>(root1, W1, IN_DIM, B1p);
    build_B_kernel<<<blocks_for(2304 * HID, 256), 256>>>(root2, W2, HID, B2p);
    build_Bdec_kernel<<<blocks_for(2 * HID * HID, 256), 256>>>(mw1);
    pack_w2_kernel<<<blocks_for(HID * (HID / 2), 256), 256>>>(mw2);

    // ===================== Layer 1 (K = 1152) =====================
    gather_agg_kernel<IN_DIM><<<blocks_for((long long)NKEYS * 32, 256), 256>>>(x);
    {
        dim3 grid(HID / 128, (N_NODES + 127) / 128);
        gemm_ps_kernel<<<grid, 256>>>(A, B1p, hp, b1, N_NODES, HID, 1152, 0);
    }
    relu_ln1_kernel<<<blocks_for((long long)N_NODES * 32, 256), 256>>>(hp, ln1g, ln1b, h1);

    // ===================== Layer 2 (K = 2304) =====================
    gather_agg_kernel<HID><<<blocks_for((long long)NKEYS * 32, 256), 256>>>(h1);
    {
        dim3 grid(HID / 128, (N_NODES + 127) / 128);
        gemm_ps_kernel<<<grid, 256>>>(A, B2p, hp, b2, N_NODES, HID, 2304, 0);
    }
    relu_ln2_kernel<<<blocks_for((long long)N_NODES * 32, 256), 256>>>(hp, ln2g, ln2b, hP, h1);

    // ===================== Decoder =====================
    {
        dim3 gp(4, (N_NODES + 127) / 128);
        gemm_ps_kernel<<<gp, 256>>>(hP, Bd, P, nullptr, N_NODES, 2 * HID, HID, 0);

        decode_fuse_kernel<<<blocks_for((long long)M_DEC * (HID / 4), 256), 256>>>(dec, mb1);

        // Fused: out = gelu(Z1 @ mw2 + mb2) @ mw3 + mb3
        dim3 g2(1, (M_DEC + 127) / 128);
        gemm_z2_final_kernel<<<g2, 256>>>(Z1, Bw2, mb2, mw3, mb3, out, M_DEC, HID);
    }
}